// round 4
// baseline (speedup 1.0000x reference)
#include <cuda_runtime.h>
#include <math.h>

#define N_NODES 50000
#define N_EDGES 800000
#define NUM_GRAPHS 64
#define IN_F 128
#define HID_F 256
#define OUT_F 256

#define SCAN_B 1024
#define SCAN_NBLK ((N_NODES + SCAN_B - 1) / SCAN_B)   // 49

// ---------------- scratch (static device globals; no runtime allocation) ----------------
__device__ int   g_degi[N_NODES];
__device__ int   g_row[N_NODES];        // CSR row start (exclusive scan of degi)
__device__ int   g_rowtmp[N_NODES];
__device__ int   g_cursor[N_NODES];
__device__ int   g_bsum[SCAN_NBLK];
__device__ int   g_boff[SCAN_NBLK];
__device__ int   g_csrc[N_EDGES];       // CSR: source node per incoming edge
__device__ float g_cw[N_EDGES];         // CSR: norm = dinv[s]*dinv[d]
__device__ float g_dinv[N_NODES];
__device__ float g_s[N_NODES];
__device__ float g_t[N_NODES];
__device__ __align__(16) float g_yA[(size_t)N_NODES * IN_F];
__device__ __align__(16) float g_yB[(size_t)N_NODES * IN_F];
__device__ float g_T1[IN_F * HID_F];
__device__ float g_M[IN_F * OUT_F];
__device__ float g_u1[HID_F];
__device__ float g_u[OUT_F];
__device__ float g_w[OUT_F];
__device__ __align__(16) float g_h[(size_t)N_NODES * OUT_F];
__device__ unsigned g_pmax[NUM_GRAPHS * OUT_F];
__device__ float g_psum[NUM_GRAPHS * OUT_F];
__device__ float g_cnt[NUM_GRAPHS];

// ---------------- helpers ----------------
__device__ __forceinline__ unsigned enc_f32(float f) {
    unsigned u = __float_as_uint(f);
    return (u & 0x80000000u) ? ~u : (u | 0x80000000u);
}
__device__ __forceinline__ float dec_f32(unsigned u) {
    return (u & 0x80000000u) ? __uint_as_float(u & 0x7FFFFFFFu) : __uint_as_float(~u);
}

// ---------------- init ----------------
__global__ void k_init() {
    int i = blockIdx.x * blockDim.x + threadIdx.x;
    if (i < N_NODES) {
        g_degi[i] = 0;
        g_cursor[i] = 0;
    }
}

__global__ void k_pool_init() {
    int i = blockIdx.x * blockDim.x + threadIdx.x;
    if (i < NUM_GRAPHS * OUT_F) {
        g_pmax[i] = 0x007FFFFFu;  // enc(-inf)
        g_psum[i] = 0.0f;
    }
    if (i < NUM_GRAPHS) g_cnt[i] = 0.0f;
}

// ---------------- CSR build (edge_index is int32, layout [2, E]) ----------------
__global__ void k_deg(const int* __restrict__ ei) {
    int e = blockIdx.x * blockDim.x + threadIdx.x;
    if (e < N_EDGES) atomicAdd(&g_degi[ei[N_EDGES + e]], 1);
}

// per-block inclusive scan (Hillis-Steele in smem); write block-exclusive prefix
__global__ void k_scan1() {
    __shared__ int sm[SCAN_B];
    int t = threadIdx.x;
    int i = blockIdx.x * SCAN_B + t;
    int v = (i < N_NODES) ? g_degi[i] : 0;
    sm[t] = v;
    __syncthreads();
#pragma unroll
    for (int off = 1; off < SCAN_B; off <<= 1) {
        int a = (t >= off) ? sm[t - off] : 0;
        __syncthreads();
        sm[t] += a;
        __syncthreads();
    }
    if (i < N_NODES) g_rowtmp[i] = sm[t] - v;    // exclusive within block
    if (t == SCAN_B - 1) g_bsum[blockIdx.x] = sm[t];
}

__global__ void k_scan2() {
    if (threadIdx.x == 0) {
        int run = 0;
        for (int b = 0; b < SCAN_NBLK; b++) { g_boff[b] = run; run += g_bsum[b]; }
    }
}

__global__ void k_scan3() {
    int i = blockIdx.x * blockDim.x + threadIdx.x;
    if (i < N_NODES) g_row[i] = g_rowtmp[i] + g_boff[i >> 10];
}

__global__ void k_dinv() {
    int i = blockIdx.x * blockDim.x + threadIdx.x;
    if (i < N_NODES) g_dinv[i] = rsqrtf((float)(g_degi[i] + 1));   // +1 self loop
}

__global__ void k_fill(const int* __restrict__ ei) {
    int e = blockIdx.x * blockDim.x + threadIdx.x;
    if (e < N_EDGES) {
        int s = ei[e];
        int d = ei[N_EDGES + e];
        int pos = g_row[d] + atomicAdd(&g_cursor[d], 1);
        g_csrc[pos] = s;
        g_cw[pos] = g_dinv[s] * g_dinv[d];
    }
}

// ---------------- scalar gathers: s, t ----------------
__global__ void k_s() {
    int i = blockIdx.x * blockDim.x + threadIdx.x;
    if (i >= N_NODES) return;
    int beg = g_row[i], end = beg + g_degi[i];
    float acc = 0.f;
    for (int k = beg; k < end; k++) acc += g_cw[k];
    float di = g_dinv[i];
    g_s[i] = acc + di * di;
}

__global__ void k_t() {
    int i = blockIdx.x * blockDim.x + threadIdx.x;
    if (i >= N_NODES) return;
    int beg = g_row[i], end = beg + g_degi[i];
    float acc = 0.f;
    for (int k = beg; k < end; k++) acc += g_cw[k] * g_s[g_csrc[k]];
    float di = g_dinv[i];
    g_t[i] = acc + di * di * g_s[i];
}

__global__ void k_cnt(const int* __restrict__ batch) {
    int i = blockIdx.x * blockDim.x + threadIdx.x;
    if (i < N_NODES) atomicAdd(&g_cnt[batch[i]], 1.0f);
}

// ---------------- aggregation (gather): yout = A(yin) at width 128 ----------------
// pass 0: x -> yA, pass 1: yA -> yB, pass 2: yB -> yA. One warp per dst node.
__global__ void __launch_bounds__(256) k_agg(const float* __restrict__ x, int pass) {
    const float* yin = pass == 0 ? x : (pass == 1 ? g_yA : g_yB);
    float* yout = pass == 1 ? g_yB : g_yA;
    int node = (blockIdx.x * blockDim.x + threadIdx.x) >> 5;
    int lane = threadIdx.x & 31;
    if (node >= N_NODES) return;
    int beg = g_row[node], end = beg + g_degi[node];
    float di = g_dinv[node];
    float d2 = di * di;

    float4 self = *((const float4*)(yin + (size_t)node * IN_F) + lane);
    float4 acc  = make_float4(d2 * self.x, d2 * self.y, d2 * self.z, d2 * self.w);
    float4 acc2 = make_float4(0.f, 0.f, 0.f, 0.f);

    int k = beg;
    for (; k + 1 < end; k += 2) {
        int s0 = g_csrc[k];     float n0 = g_cw[k];
        int s1 = g_csrc[k + 1]; float n1 = g_cw[k + 1];
        float4 v0 = *((const float4*)(yin + (size_t)s0 * IN_F) + lane);
        float4 v1 = *((const float4*)(yin + (size_t)s1 * IN_F) + lane);
        acc.x  += n0 * v0.x; acc.y  += n0 * v0.y; acc.z  += n0 * v0.z; acc.w  += n0 * v0.w;
        acc2.x += n1 * v1.x; acc2.y += n1 * v1.y; acc2.z += n1 * v1.z; acc2.w += n1 * v1.w;
    }
    if (k < end) {
        int s0 = g_csrc[k]; float n0 = g_cw[k];
        float4 v0 = *((const float4*)(yin + (size_t)s0 * IN_F) + lane);
        acc.x += n0 * v0.x; acc.y += n0 * v0.y; acc.z += n0 * v0.z; acc.w += n0 * v0.w;
    }
    acc.x += acc2.x; acc.y += acc2.y; acc.z += acc2.z; acc.w += acc2.w;
    *((float4*)(yout + (size_t)node * IN_F) + lane) = acc;
}

// ---------------- small weight products ----------------
__global__ void k_wprod1(const float* __restrict__ W1, const float* __restrict__ W2,
                         const float* __restrict__ b1) {
    int j = threadIdx.x;
    int i = blockIdx.x;
    if (i < IN_F) {
        float acc = 0.f;
        for (int k = 0; k < HID_F; k++) acc += W1[i * HID_F + k] * W2[k * HID_F + j];
        g_T1[i * HID_F + j] = acc;
    } else {
        float acc = 0.f;
        for (int k = 0; k < HID_F; k++) acc += b1[k] * W2[k * HID_F + j];
        g_u1[j] = acc;
    }
}

__global__ void k_wprod2(const float* __restrict__ W3, const float* __restrict__ b2) {
    int j = threadIdx.x;
    int i = blockIdx.x;
    if (i < IN_F) {
        float acc = 0.f;
        for (int k = 0; k < HID_F; k++) acc += g_T1[i * HID_F + k] * W3[k * OUT_F + j];
        g_M[i * OUT_F + j] = acc;
    } else {
        float a = 0.f, b = 0.f;
        for (int k = 0; k < HID_F; k++) {
            float w3 = W3[k * OUT_F + j];
            a += g_u1[k] * w3;
            b += b2[k] * w3;
        }
        g_u[j] = a;
        g_w[j] = b;
    }
}

// ---------------- final GEMM: h = y3 @ M + t*u^T + s*w^T + b3 ----------------
#define BM 128
#define BN 128
#define BK 32
__global__ void __launch_bounds__(256) k_gemm(const float* __restrict__ b3) {
    __shared__ float As[BM][BK + 1];
    __shared__ float Bs[BK][BN + 4];
    const float* A = g_yA;   // y3 lives in g_yA after 3 passes
    const float* B = g_M;
    int bx = blockIdx.y;
    int row0 = blockIdx.x * BM;
    int tid = threadIdx.x;
    int tx = tid & 15, ty = tid >> 4;
    float acc[8][8];
#pragma unroll
    for (int i = 0; i < 8; i++)
#pragma unroll
        for (int j = 0; j < 8; j++) acc[i][j] = 0.f;

    for (int kb = 0; kb < IN_F; kb += BK) {
#pragma unroll
        for (int i = 0; i < 4; i++) {
            int id = tid + i * 256;
            int r = id >> 3;
            int c = (id & 7) * 4;
            float4 v = make_float4(0.f, 0.f, 0.f, 0.f);
            int gr = row0 + r;
            if (gr < N_NODES) v = *(const float4*)(A + (size_t)gr * IN_F + kb + c);
            As[r][c] = v.x; As[r][c + 1] = v.y; As[r][c + 2] = v.z; As[r][c + 3] = v.w;
        }
#pragma unroll
        for (int i = 0; i < 4; i++) {
            int id = tid + i * 256;
            int kr = id >> 5;
            int c = (id & 31) * 4;
            float4 v = *(const float4*)(B + (size_t)(kb + kr) * OUT_F + bx * BN + c);
            Bs[kr][c] = v.x; Bs[kr][c + 1] = v.y; Bs[kr][c + 2] = v.z; Bs[kr][c + 3] = v.w;
        }
        __syncthreads();
#pragma unroll
        for (int k = 0; k < BK; k++) {
            float ra[8], rb[8];
#pragma unroll
            for (int i = 0; i < 8; i++) ra[i] = As[ty * 8 + i][k];
#pragma unroll
            for (int j = 0; j < 8; j++) rb[j] = Bs[k][tx * 8 + j];
#pragma unroll
            for (int i = 0; i < 8; i++)
#pragma unroll
                for (int j = 0; j < 8; j++) acc[i][j] += ra[i] * rb[j];
        }
        __syncthreads();
    }
#pragma unroll
    for (int i = 0; i < 8; i++) {
        int gr = row0 + ty * 8 + i;
        if (gr >= N_NODES) break;
        float tr = g_t[gr], sr = g_s[gr];
#pragma unroll
        for (int j = 0; j < 8; j++) {
            int gc = bx * BN + tx * 8 + j;
            g_h[(size_t)gr * OUT_F + gc] = acc[i][j] + tr * g_u[gc] + sr * g_w[gc] + b3[gc];
        }
    }
}

// ---------------- pooling over sorted batch ----------------
__global__ void k_pool(const int* __restrict__ batch) {
    int c = threadIdx.x;                   // 256 cols
    int row0 = blockIdx.x * 128;
    int rend = min(row0 + 128, N_NODES);
    if (row0 >= N_NODES) return;
    int curg = batch[row0];
    float rmax = -INFINITY, rsum = 0.f;
    for (int r = row0; r < rend; r++) {
        int g = batch[r];
        if (g != curg) {
            atomicMax(&g_pmax[curg * OUT_F + c], enc_f32(rmax));
            atomicAdd(&g_psum[curg * OUT_F + c], rsum);
            curg = g; rmax = -INFINITY; rsum = 0.f;
        }
        float v = g_h[(size_t)r * OUT_F + c];
        rmax = fmaxf(rmax, v);
        rsum += v;
    }
    atomicMax(&g_pmax[curg * OUT_F + c], enc_f32(rmax));
    atomicAdd(&g_psum[curg * OUT_F + c], rsum);
}

__global__ void k_out(float* __restrict__ out) {
    int g = blockIdx.x;
    int c = threadIdx.x;                   // 512 threads
    if (c < OUT_F) {
        out[g * 2 * OUT_F + c] = dec_f32(g_pmax[g * OUT_F + c]);
    } else {
        int cc = c - OUT_F;
        float cnt = g_cnt[g];
        out[g * 2 * OUT_F + OUT_F + cc] = g_psum[g * OUT_F + cc] / fmaxf(cnt, 1.0f);
    }
}

// ---------------- launch ----------------
extern "C" void kernel_launch(void* const* d_in, const int* in_sizes, int n_in,
                              void* d_out, int out_size) {
    const float* x = (const float*)d_in[0];
    const int* ei = (const int*)d_in[1];       // int32! (JAX x64 disabled)
    const int* batch = (const int*)d_in[2];    // int32!
    const float* W1 = (const float*)d_in[3];
    const float* b1 = (const float*)d_in[4];
    const float* W2 = (const float*)d_in[5];
    const float* b2 = (const float*)d_in[6];
    const float* W3 = (const float*)d_in[7];
    const float* b3 = (const float*)d_in[8];
    float* out = (float*)d_out;

    const int NT = 256;
    int nb_nodes = (N_NODES + NT - 1) / NT;
    int nb_edges = (N_EDGES + NT - 1) / NT;
    int nb_aggw  = (N_NODES * 32 + NT - 1) / NT;     // one warp per node

    // CSR build
    k_init<<<nb_nodes, NT>>>();
    k_pool_init<<<(NUM_GRAPHS * OUT_F + NT - 1) / NT, NT>>>();
    k_deg<<<nb_edges, NT>>>(ei);
    k_scan1<<<SCAN_NBLK, SCAN_B>>>();
    k_scan2<<<1, 32>>>();
    k_scan3<<<nb_nodes, NT>>>();
    k_dinv<<<nb_nodes, NT>>>();
    k_fill<<<nb_edges, NT>>>(ei);

    // scalar propagations
    k_s<<<nb_nodes, NT>>>();
    k_t<<<nb_nodes, NT>>>();
    k_cnt<<<nb_nodes, NT>>>(batch);

    // three aggregation passes at width 128 (gather, no atomics)
    k_agg<<<nb_aggw, NT>>>(x, 0);
    k_agg<<<nb_aggw, NT>>>(x, 1);
    k_agg<<<nb_aggw, NT>>>(x, 2);

    // weight pre-products (tiny)
    k_wprod1<<<IN_F + 1, HID_F>>>(W1, W2, b1);
    k_wprod2<<<IN_F + 1, OUT_F>>>(W3, b2);

    // final fused GEMM: h = y3 @ M + t u^T + s w^T + b3
    dim3 gemm_grid((N_NODES + BM - 1) / BM, OUT_F / BN);
    k_gemm<<<gemm_grid, 256>>>(b3);

    // pooling
    k_pool<<<(N_NODES + 127) / 128, OUT_F>>>(batch);
    k_out<<<NUM_GRAPHS, 2 * OUT_F>>>(out);
}

// round 6
// speedup vs baseline: 1.0708x; 1.0708x over previous
#include <cuda_runtime.h>
#include <math.h>

#define N_NODES 50000
#define N_EDGES 800000
#define NUM_GRAPHS 64
#define IN_F 128
#define HID_F 256
#define OUT_F 256

#define SCAN_B 1024
#define SCAN_NBLK ((N_NODES + SCAN_B - 1) / SCAN_B)   // 49

// ---------------- scratch (static device globals) ----------------
__device__ int   g_degi[N_NODES];
__device__ int   g_row[N_NODES];
__device__ int   g_rowtmp[N_NODES];
__device__ int   g_cursor[N_NODES];
__device__ int   g_bsum[SCAN_NBLK];
__device__ int   g_boff[SCAN_NBLK];
__device__ int   g_csrc[N_EDGES];
__device__ float g_cw[N_EDGES];
__device__ float g_dinv[N_NODES];
__device__ float g_sacc[N_NODES];
__device__ float g_s[N_NODES];
__device__ float g_t[N_NODES];
__device__ __align__(16) float g_yA[(size_t)N_NODES * IN_F];
__device__ __align__(16) float g_yB[(size_t)N_NODES * IN_F];
__device__ float g_T1[IN_F * HID_F];
__device__ float g_M[IN_F * OUT_F];
__device__ float g_u1[HID_F];
__device__ float g_u[OUT_F];
__device__ float g_w[OUT_F];
__device__ unsigned g_pmax[NUM_GRAPHS * OUT_F];
__device__ float g_psum[NUM_GRAPHS * OUT_F];
__device__ float g_cnt[NUM_GRAPHS];

// ---------------- helpers ----------------
__device__ __forceinline__ unsigned enc_f32(float f) {
    unsigned u = __float_as_uint(f);
    return (u & 0x80000000u) ? ~u : (u | 0x80000000u);
}
__device__ __forceinline__ float dec_f32(unsigned u) {
    return (u & 0x80000000u) ? __uint_as_float(u & 0x7FFFFFFFu) : __uint_as_float(~u);
}

// ---------------- init ----------------
__global__ void k_init() {
    int i = blockIdx.x * blockDim.x + threadIdx.x;
    if (i < N_NODES) {
        g_degi[i] = 0;
        g_cursor[i] = 0;
        g_sacc[i] = 0.0f;
    }
}

__global__ void k_pool_init() {
    int i = blockIdx.x * blockDim.x + threadIdx.x;
    if (i < NUM_GRAPHS * OUT_F) {
        g_pmax[i] = 0x007FFFFFu;  // enc(-inf)
        g_psum[i] = 0.0f;
    }
    if (i < NUM_GRAPHS) g_cnt[i] = 0.0f;
}

// ---------------- CSR build (edge_index int32, layout [2, E]) ----------------
__global__ void k_deg(const int* __restrict__ ei) {
    int e = blockIdx.x * blockDim.x + threadIdx.x;
    if (e < N_EDGES) atomicAdd(&g_degi[ei[N_EDGES + e]], 1);
}

__global__ void k_scan1() {
    __shared__ int sm[SCAN_B];
    int t = threadIdx.x;
    int i = blockIdx.x * SCAN_B + t;
    int v = (i < N_NODES) ? g_degi[i] : 0;
    sm[t] = v;
    __syncthreads();
#pragma unroll
    for (int off = 1; off < SCAN_B; off <<= 1) {
        int a = (t >= off) ? sm[t - off] : 0;
        __syncthreads();
        sm[t] += a;
        __syncthreads();
    }
    if (i < N_NODES) g_rowtmp[i] = sm[t] - v;
    if (t == SCAN_B - 1) g_bsum[blockIdx.x] = sm[t];
}

__global__ void k_scan2() {
    if (threadIdx.x == 0) {
        int run = 0;
        for (int b = 0; b < SCAN_NBLK; b++) { g_boff[b] = run; run += g_bsum[b]; }
    }
}

// scan3 + dinv fused
__global__ void k_scan3() {
    int i = blockIdx.x * blockDim.x + threadIdx.x;
    if (i < N_NODES) {
        g_row[i] = g_rowtmp[i] + g_boff[i >> 10];
        g_dinv[i] = rsqrtf((float)(g_degi[i] + 1));
    }
}

// fill CSR + accumulate s (sum of incoming norms) in the same pass
__global__ void k_fill(const int* __restrict__ ei) {
    int e = blockIdx.x * blockDim.x + threadIdx.x;
    if (e < N_EDGES) {
        int s = ei[e];
        int d = ei[N_EDGES + e];
        float w = g_dinv[s] * g_dinv[d];
        int pos = g_row[d] + atomicAdd(&g_cursor[d], 1);
        g_csrc[pos] = s;
        g_cw[pos] = w;
        atomicAdd(&g_sacc[d], w);
    }
}

// finalize s + per-graph node counts
__global__ void k_sfin_cnt(const int* __restrict__ batch) {
    int i = blockIdx.x * blockDim.x + threadIdx.x;
    if (i < N_NODES) {
        float di = g_dinv[i];
        g_s[i] = g_sacc[i] + di * di;
        atomicAdd(&g_cnt[batch[i]], 1.0f);
    }
}

__global__ void k_t() {
    int i = blockIdx.x * blockDim.x + threadIdx.x;
    if (i >= N_NODES) return;
    int beg = g_row[i], end = beg + g_degi[i];
    float acc = 0.f;
    for (int k = beg; k < end; k++) acc += g_cw[k] * g_s[g_csrc[k]];
    float di = g_dinv[i];
    g_t[i] = acc + di * di * g_s[i];
}

// ---------------- aggregation (gather): yout = A(yin), width 128 ----------------
// pass 0: x -> yA, pass 1: yA -> yB, pass 2: yB -> yA. One warp per dst node.
__global__ void __launch_bounds__(256) k_agg(const float* __restrict__ x, int pass) {
    const float* yin = pass == 0 ? x : (pass == 1 ? g_yA : g_yB);
    float* yout = pass == 1 ? g_yB : g_yA;
    int node = (blockIdx.x * blockDim.x + threadIdx.x) >> 5;
    int lane = threadIdx.x & 31;
    if (node >= N_NODES) return;
    int beg = g_row[node], end = beg + g_degi[node];
    float di = g_dinv[node];
    float d2 = di * di;

    float4 self = *((const float4*)(yin + (size_t)node * IN_F) + lane);
    float4 a0 = make_float4(d2 * self.x, d2 * self.y, d2 * self.z, d2 * self.w);
    float4 a1 = make_float4(0.f, 0.f, 0.f, 0.f);
    float4 a2 = make_float4(0.f, 0.f, 0.f, 0.f);
    float4 a3 = make_float4(0.f, 0.f, 0.f, 0.f);

    int k = beg;
    for (; k + 3 < end; k += 4) {
        int s0 = g_csrc[k];     float n0 = g_cw[k];
        int s1 = g_csrc[k + 1]; float n1 = g_cw[k + 1];
        int s2 = g_csrc[k + 2]; float n2 = g_cw[k + 2];
        int s3 = g_csrc[k + 3]; float n3 = g_cw[k + 3];
        float4 v0 = *((const float4*)(yin + (size_t)s0 * IN_F) + lane);
        float4 v1 = *((const float4*)(yin + (size_t)s1 * IN_F) + lane);
        float4 v2 = *((const float4*)(yin + (size_t)s2 * IN_F) + lane);
        float4 v3 = *((const float4*)(yin + (size_t)s3 * IN_F) + lane);
        a0.x += n0 * v0.x; a0.y += n0 * v0.y; a0.z += n0 * v0.z; a0.w += n0 * v0.w;
        a1.x += n1 * v1.x; a1.y += n1 * v1.y; a1.z += n1 * v1.z; a1.w += n1 * v1.w;
        a2.x += n2 * v2.x; a2.y += n2 * v2.y; a2.z += n2 * v2.z; a2.w += n2 * v2.w;
        a3.x += n3 * v3.x; a3.y += n3 * v3.y; a3.z += n3 * v3.z; a3.w += n3 * v3.w;
    }
    for (; k < end; k++) {
        int s0 = g_csrc[k]; float n0 = g_cw[k];
        float4 v0 = *((const float4*)(yin + (size_t)s0 * IN_F) + lane);
        a0.x += n0 * v0.x; a0.y += n0 * v0.y; a0.z += n0 * v0.z; a0.w += n0 * v0.w;
    }
    a0.x += a1.x + a2.x + a3.x;
    a0.y += a1.y + a2.y + a3.y;
    a0.z += a1.z + a2.z + a3.z;
    a0.w += a1.w + a2.w + a3.w;
    *((float4*)(yout + (size_t)node * IN_F) + lane) = a0;
}

// ---------------- small weight products ----------------
__global__ void k_wprod1(const float* __restrict__ W1, const float* __restrict__ W2,
                         const float* __restrict__ b1) {
    int j = threadIdx.x;
    int i = blockIdx.x;
    if (i < IN_F) {
        float acc = 0.f;
        for (int k = 0; k < HID_F; k++) acc += W1[i * HID_F + k] * W2[k * HID_F + j];
        g_T1[i * HID_F + j] = acc;
    } else {
        float acc = 0.f;
        for (int k = 0; k < HID_F; k++) acc += b1[k] * W2[k * HID_F + j];
        g_u1[j] = acc;
    }
}

__global__ void k_wprod2(const float* __restrict__ W3, const float* __restrict__ b2) {
    int j = threadIdx.x;
    int i = blockIdx.x;
    if (i < IN_F) {
        float acc = 0.f;
        for (int k = 0; k < HID_F; k++) acc += g_T1[i * HID_F + k] * W3[k * OUT_F + j];
        g_M[i * OUT_F + j] = acc;
    } else {
        float a = 0.f, b = 0.f;
        for (int k = 0; k < HID_F; k++) {
            float w3 = W3[k * OUT_F + j];
            a += g_u1[k] * w3;
            b += b2[k] * w3;
        }
        g_u[j] = a;
        g_w[j] = b;
    }
}

// ---------------- fused GEMM + pooling ----------------
// h = y3 @ M + t*u^T + s*w^T + b3, pooled directly into g_pmax / g_psum.
#define BM 128
#define BN 128
#define BK 32
__global__ void __launch_bounds__(256) k_gemm_pool(const float* __restrict__ b3,
                                                   const int* __restrict__ batch) {
    __shared__ float As[BM][BK + 1];
    __shared__ float Bs[BK][BN + 4];
    const float* A = g_yA;   // y3 lives in g_yA after 3 passes
    const float* B = g_M;
    int bx = blockIdx.y;
    int row0 = blockIdx.x * BM;
    int tid = threadIdx.x;
    int tx = tid & 15, ty = tid >> 4;
    float acc[8][8];
#pragma unroll
    for (int i = 0; i < 8; i++)
#pragma unroll
        for (int j = 0; j < 8; j++) acc[i][j] = 0.f;

    for (int kb = 0; kb < IN_F; kb += BK) {
#pragma unroll
        for (int i = 0; i < 4; i++) {
            int id = tid + i * 256;
            int r = id >> 3;
            int c = (id & 7) * 4;
            float4 v = make_float4(0.f, 0.f, 0.f, 0.f);
            int gr = row0 + r;
            if (gr < N_NODES) v = *(const float4*)(A + (size_t)gr * IN_F + kb + c);
            As[r][c] = v.x; As[r][c + 1] = v.y; As[r][c + 2] = v.z; As[r][c + 3] = v.w;
        }
#pragma unroll
        for (int i = 0; i < 4; i++) {
            int id = tid + i * 256;
            int kr = id >> 5;
            int c = (id & 31) * 4;
            float4 v = *(const float4*)(B + (size_t)(kb + kr) * OUT_F + bx * BN + c);
            Bs[kr][c] = v.x; Bs[kr][c + 1] = v.y; Bs[kr][c + 2] = v.z; Bs[kr][c + 3] = v.w;
        }
        __syncthreads();
#pragma unroll
        for (int k = 0; k < BK; k++) {
            float ra[8], rb[8];
#pragma unroll
            for (int i = 0; i < 8; i++) ra[i] = As[ty * 8 + i][k];
#pragma unroll
            for (int j = 0; j < 8; j++) rb[j] = Bs[k][tx * 8 + j];
#pragma unroll
            for (int i = 0; i < 8; i++)
#pragma unroll
                for (int j = 0; j < 8; j++) acc[i][j] += ra[i] * rb[j];
        }
        __syncthreads();
    }

    // epilogue: rank-1 terms + bias, then pooled reduction (batch is sorted)
    float uj[8], wj[8], bj[8];
    int gc0 = bx * BN + tx * 8;
#pragma unroll
    for (int j = 0; j < 8; j++) {
        uj[j] = g_u[gc0 + j];
        wj[j] = g_w[gc0 + j];
        bj[j] = b3[gc0 + j];
    }

    int curg = -1;
    float rmax[8], rsum[8];
#pragma unroll
    for (int i = 0; i < 8; i++) {
        int gr = row0 + ty * 8 + i;
        if (gr < N_NODES) {
            int g = batch[gr];
            float tr = g_t[gr], sr = g_s[gr];
            if (g != curg) {
                if (curg >= 0) {
#pragma unroll
                    for (int j = 0; j < 8; j++) {
                        atomicMax(&g_pmax[curg * OUT_F + gc0 + j], enc_f32(rmax[j]));
                        atomicAdd(&g_psum[curg * OUT_F + gc0 + j], rsum[j]);
                    }
                }
                curg = g;
#pragma unroll
                for (int j = 0; j < 8; j++) { rmax[j] = -INFINITY; rsum[j] = 0.f; }
            }
#pragma unroll
            for (int j = 0; j < 8; j++) {
                float h = acc[i][j] + tr * uj[j] + sr * wj[j] + bj[j];
                rmax[j] = fmaxf(rmax[j], h);
                rsum[j] += h;
            }
        }
    }
    if (curg >= 0) {
#pragma unroll
        for (int j = 0; j < 8; j++) {
            atomicMax(&g_pmax[curg * OUT_F + gc0 + j], enc_f32(rmax[j]));
            atomicAdd(&g_psum[curg * OUT_F + gc0 + j], rsum[j]);
        }
    }
}

__global__ void k_out(float* __restrict__ out) {
    int g = blockIdx.x;
    int c = threadIdx.x;                   // 512 threads
    if (c < OUT_F) {
        out[g * 2 * OUT_F + c] = dec_f32(g_pmax[g * OUT_F + c]);
    } else {
        int cc = c - OUT_F;
        float cnt = g_cnt[g];
        out[g * 2 * OUT_F + OUT_F + cc] = g_psum[g * OUT_F + cc] / fmaxf(cnt, 1.0f);
    }
}

// ---------------- launch ----------------
extern "C" void kernel_launch(void* const* d_in, const int* in_sizes, int n_in,
                              void* d_out, int out_size) {
    const float* x = (const float*)d_in[0];
    const int* ei = (const int*)d_in[1];       // int32 (JAX x64 disabled)
    const int* batch = (const int*)d_in[2];    // int32
    const float* W1 = (const float*)d_in[3];
    const float* b1 = (const float*)d_in[4];
    const float* W2 = (const float*)d_in[5];
    const float* b2 = (const float*)d_in[6];
    const float* W3 = (const float*)d_in[7];
    const float* b3 = (const float*)d_in[8];
    float* out = (float*)d_out;

    const int NT = 256;
    int nb_nodes = (N_NODES + NT - 1) / NT;
    int nb_edges = (N_EDGES + NT - 1) / NT;
    int nb_aggw  = (N_NODES * 32 + NT - 1) / NT;     // one warp per node

    // CSR build
    k_init<<<nb_nodes, NT>>>();
    k_pool_init<<<(NUM_GRAPHS * OUT_F + NT - 1) / NT, NT>>>();
    k_deg<<<nb_edges, NT>>>(ei);
    k_scan1<<<SCAN_NBLK, SCAN_B>>>();
    k_scan2<<<1, 32>>>();
    k_scan3<<<nb_nodes, NT>>>();
    k_fill<<<nb_edges, NT>>>(ei);

    // scalar propagations
    k_sfin_cnt<<<nb_nodes, NT>>>(batch);
    k_t<<<nb_nodes, NT>>>();

    // three aggregation passes at width 128 (gather, no feature atomics)
    k_agg<<<nb_aggw, NT>>>(x, 0);
    k_agg<<<nb_aggw, NT>>>(x, 1);
    k_agg<<<nb_aggw, NT>>>(x, 2);

    // weight pre-products (tiny)
    k_wprod1<<<IN_F + 1, HID_F>>>(W1, W2, b1);
    k_wprod2<<<IN_F + 1, OUT_F>>>(W3, b2);

    // fused GEMM + pooling
    dim3 gemm_grid((N_NODES + BM - 1) / BM, OUT_F / BN);
    k_gemm_pool<<<gemm_grid, 256>>>(b3, batch);

    k_out<<<NUM_GRAPHS, 2 * OUT_F>>>(out);
}